// round 2
// baseline (speedup 1.0000x reference)
#include <cuda_runtime.h>

#define NUQ 100000
#define NIQ 50000
#define NEQ 1000000
#define NTOT (NUQ + NIQ)

// ---------------- scratch (device globals; no allocation allowed) ----------------
__device__ int   g_deg_u[NUQ];
__device__ int   g_deg_i[NIQ];
__device__ int   g_rp_u[NUQ + 1];
__device__ int   g_rp_i[NIQ + 1];
__device__ int   g_cur_u[NUQ];
__device__ int   g_cur_i[NIQ];
__device__ int   g_col_u[NEQ];   // per-user neighbor items (CSR by user)
__device__ int   g_col_i[NEQ];   // per-item neighbor users (CSR by item)
__device__ float g_su[NUQ], g_iu[NUQ];   // deg_u^-1/2, deg_u^-1
__device__ float g_si[NIQ], g_ii[NIQ];   // deg_i^-1/2, deg_i^-1
__device__ float g_cur[(size_t)NTOT * 64];   // current embeddings (users then items)
__device__ float g_acc[(size_t)NTOT * 64];   // running sum for the mean
__device__ float g_E[(size_t)NTOT * 64];     // E_items [0,NI), E_users [NI,NI+NU)
__device__ float g_gp[(size_t)NTOT * 128];   // per row: 32 groups of (g0,g1,p0,p1)

// ---------------- helpers ----------------
__device__ __forceinline__ void fma2(unsigned long long& acc, unsigned long long a,
                                     unsigned long long b) {
    asm("fma.rn.f32x2 %0, %1, %2, %0;" : "+l"(acc) : "l"(a), "l"(b));
}
__device__ __forceinline__ float2 unpack2(unsigned long long v) {
    float2 r;
    asm("mov.b64 {%0, %1}, %2;" : "=f"(r.x), "=f"(r.y) : "l"(v));
    return r;
}
__device__ __forceinline__ float lrelu(float x) { return x > 0.f ? x : 0.2f * x; }

// ---------------- setup kernels ----------------
__global__ void k_zero() {
    int i = blockIdx.x * blockDim.x + threadIdx.x;
    int st = gridDim.x * blockDim.x;
    for (int j = i; j < NUQ; j += st) { g_deg_u[j] = 0; g_cur_u[j] = 0; }
    for (int j = i; j < NIQ; j += st) { g_deg_i[j] = 0; g_cur_i[j] = 0; }
}

__global__ void k_deg(const int* __restrict__ eu, const int* __restrict__ ei) {
    int e = blockIdx.x * blockDim.x + threadIdx.x;
    if (e < NEQ) {
        atomicAdd(&g_deg_u[eu[e]], 1);
        atomicAdd(&g_deg_i[ei[e]], 1);
    }
}

__global__ void k_scalars() {
    int j = blockIdx.x * blockDim.x + threadIdx.x;
    if (j < NUQ) {
        int d = g_deg_u[j];
        g_su[j] = d > 0 ? rsqrtf((float)d) : 0.f;
        g_iu[j] = d > 0 ? 1.f / (float)d : 0.f;
    }
    if (j < NIQ) {
        int d = g_deg_i[j];
        g_si[j] = d > 0 ? rsqrtf((float)d) : 0.f;
        g_ii[j] = d > 0 ? 1.f / (float)d : 0.f;
    }
}

// exclusive scan of degrees -> row pointers; block 0: items, block 1: users
__global__ void k_scan() {
    __shared__ int s[1024];
    const int  N   = (blockIdx.x == 0) ? NIQ : NUQ;
    const int* deg = (blockIdx.x == 0) ? g_deg_i : g_deg_u;
    int*       rp  = (blockIdx.x == 0) ? g_rp_i : g_rp_u;
    int carry = 0;
    for (int base = 0; base < N; base += 1024) {
        int idx = base + threadIdx.x;
        int v = (idx < N) ? deg[idx] : 0;
        s[threadIdx.x] = v;
        __syncthreads();
        for (int off = 1; off < 1024; off <<= 1) {
            int t = (threadIdx.x >= off) ? s[threadIdx.x - off] : 0;
            __syncthreads();
            s[threadIdx.x] += t;
            __syncthreads();
        }
        if (idx < N) rp[idx] = carry + s[threadIdx.x] - v;
        carry += s[1023];
        __syncthreads();
    }
    if (threadIdx.x == 0) rp[N] = carry;
}

__global__ void k_fill(const int* __restrict__ eu, const int* __restrict__ ei) {
    int e = blockIdx.x * blockDim.x + threadIdx.x;
    if (e < NEQ) {
        int u = eu[e], it = ei[e];
        int pu = g_rp_u[u] + atomicAdd(&g_cur_u[u], 1);
        g_col_u[pu] = it;
        int pi = g_rp_i[it] + atomicAdd(&g_cur_i[it], 1);
        g_col_i[pi] = u;
    }
}

__global__ void k_init(const float* __restrict__ ue, const float* __restrict__ ie) {
    int j = blockIdx.x * blockDim.x + threadIdx.x;
    int st = gridDim.x * blockDim.x;
    const int totu = NUQ * 16;        // float4 count of user part
    const int tot = NTOT * 16;
    const float4* u4 = (const float4*)ue;
    const float4* i4 = (const float4*)ie;
    for (; j < tot; j += st) {
        float4 v = (j < totu) ? u4[j] : i4[j - totu];
        ((float4*)g_cur)[j] = v;
        ((float4*)g_acc)[j] = v;
    }
}

// ---------------- graph stages: warp = 2 rows, 16 lanes x float4 per row ----------------
__global__ __launch_bounds__(256) void k_stage1() {
    int gw = (blockIdx.x * 256 + threadIdx.x) >> 5;
    int lane = threadIdx.x & 31;
    int sub = lane >> 4, l16 = lane & 15;
    int r = gw * 2 + sub;
    if (r >= NTOT) return;

    int start, end;
    const int* col;
    const float* wts;
    const float* src;
    float sc;
    float* dst;
    if (r < NIQ) {            // item rows: E_items[i] = ii[i] * sum su[u]*cur_u[u]
        start = g_rp_i[r]; end = g_rp_i[r + 1];
        col = g_col_i; wts = g_su; src = g_cur;
        sc = g_ii[r]; dst = g_E + (size_t)r * 64;
    } else {                  // user rows: E_users[u] = iu[u] * sum si[i]*cur_i[i]
        int u = r - NIQ;
        start = g_rp_u[u]; end = g_rp_u[u + 1];
        col = g_col_u; wts = g_si; src = g_cur + (size_t)NUQ * 64;
        sc = g_iu[u]; dst = g_E + (size_t)(NIQ + u) * 64;
    }

    float4 a = make_float4(0.f, 0.f, 0.f, 0.f);
    int e = start;
    for (; e + 4 <= end; e += 4) {
        int n0 = col[e], n1 = col[e + 1], n2 = col[e + 2], n3 = col[e + 3];
        float w0 = wts[n0], w1 = wts[n1], w2 = wts[n2], w3 = wts[n3];
        float4 v0 = *(const float4*)(src + (size_t)n0 * 64 + l16 * 4);
        float4 v1 = *(const float4*)(src + (size_t)n1 * 64 + l16 * 4);
        float4 v2 = *(const float4*)(src + (size_t)n2 * 64 + l16 * 4);
        float4 v3 = *(const float4*)(src + (size_t)n3 * 64 + l16 * 4);
        a.x += w0 * v0.x + w1 * v1.x + w2 * v2.x + w3 * v3.x;
        a.y += w0 * v0.y + w1 * v1.y + w2 * v2.y + w3 * v3.y;
        a.z += w0 * v0.z + w1 * v1.z + w2 * v2.z + w3 * v3.z;
        a.w += w0 * v0.w + w1 * v1.w + w2 * v2.w + w3 * v3.w;
    }
    for (; e < end; e++) {
        int n = col[e];
        float w = wts[n];
        float4 v = *(const float4*)(src + (size_t)n * 64 + l16 * 4);
        a.x += w * v.x; a.y += w * v.y; a.z += w * v.z; a.w += w * v.w;
    }
    *(float4*)(dst + l16 * 4) = make_float4(a.x * sc, a.y * sc, a.z * sc, a.w * sc);
}

__global__ __launch_bounds__(256) void k_stage2() {
    int gw = (blockIdx.x * 256 + threadIdx.x) >> 5;
    int lane = threadIdx.x & 31;
    int sub = lane >> 4, l16 = lane & 15;
    int r = gw * 2 + sub;
    if (r >= NTOT) return;

    int start, end;
    const int* col;
    const float* src;
    float sc;
    if (r < NUQ) {            // user rows: g_u = su[u] * sum E_items[neighbors]
        start = g_rp_u[r]; end = g_rp_u[r + 1];
        col = g_col_u; src = g_E; sc = g_su[r];
    } else {                  // item rows: g_i = si[i] * sum E_users[neighbors]
        int i = r - NUQ;
        start = g_rp_i[i]; end = g_rp_i[i + 1];
        col = g_col_i; src = g_E + (size_t)NIQ * 64; sc = g_si[i];
    }

    float4 a = make_float4(0.f, 0.f, 0.f, 0.f);
    int e = start;
    for (; e + 4 <= end; e += 4) {
        int n0 = col[e], n1 = col[e + 1], n2 = col[e + 2], n3 = col[e + 3];
        float4 v0 = *(const float4*)(src + (size_t)n0 * 64 + l16 * 4);
        float4 v1 = *(const float4*)(src + (size_t)n1 * 64 + l16 * 4);
        float4 v2 = *(const float4*)(src + (size_t)n2 * 64 + l16 * 4);
        float4 v3 = *(const float4*)(src + (size_t)n3 * 64 + l16 * 4);
        a.x += v0.x + v1.x + v2.x + v3.x;
        a.y += v0.y + v1.y + v2.y + v3.y;
        a.z += v0.z + v1.z + v2.z + v3.z;
        a.w += v0.w + v1.w + v2.w + v3.w;
    }
    for (; e < end; e++) {
        int n = col[e];
        float4 v = *(const float4*)(src + (size_t)n * 64 + l16 * 4);
        a.x += v.x; a.y += v.y; a.z += v.z; a.w += v.w;
    }
    float4 g4 = make_float4(a.x * sc, a.y * sc, a.z * sc, a.w * sc);
    float4 x4 = *(const float4*)(g_cur + (size_t)r * 64 + l16 * 4);
    // per k2 group: (g_2k2, g_2k2+1, p_2k2, p_2k2+1)  (k = 4*l16 .. 4*l16+3)
    float* gpo = g_gp + (size_t)r * 128 + l16 * 8;
    *(float4*)gpo       = make_float4(g4.x, g4.y, g4.x * x4.x, g4.y * x4.y);
    *(float4*)(gpo + 4) = make_float4(g4.z, g4.w, g4.z * x4.z, g4.w * x4.w);
}

// ---------------- epilogue: dual GEMV + leaky relu + row norm + mean accum ----------------
__global__ __launch_bounds__(256) void k_epi(const float* __restrict__ Wgc,
                                             const float* __restrict__ bgc,
                                             const float* __restrict__ Wbi,
                                             const float* __restrict__ bbi,
                                             float* __restrict__ out, int last) {
    // swg[k2][lane] = (W[lane][2k2], W[lane][2k2+1], W[lane+32][2k2], W[lane+32][2k2+1])
    __shared__ float4 swg[32][32];
    __shared__ float4 swb[32][32];
    __shared__ float sbg[64], sbb[64];
    for (int idx = threadIdx.x; idx < 1024; idx += 256) {
        int d = idx >> 5, k2 = idx & 31, k = 2 * k2;
        swg[k2][d] = make_float4(Wgc[d * 64 + k], Wgc[d * 64 + k + 1],
                                 Wgc[(d + 32) * 64 + k], Wgc[(d + 32) * 64 + k + 1]);
        swb[k2][d] = make_float4(Wbi[d * 64 + k], Wbi[d * 64 + k + 1],
                                 Wbi[(d + 32) * 64 + k], Wbi[(d + 32) * 64 + k + 1]);
    }
    if (threadIdx.x < 64) { sbg[threadIdx.x] = bgc[threadIdx.x]; sbb[threadIdx.x] = bbi[threadIdx.x]; }
    __syncthreads();

    int lane = threadIdx.x & 31;
    int gw = (blockIdx.x * 256 + threadIdx.x) >> 5;
    int nw = gridDim.x * 8;
    const int ntask = NTOT / 8;   // 150000 % 8 == 0

    for (int t = gw; t < ntask; t += nw) {
        int r0 = t * 8;
        unsigned long long agl[8], agh[8], abl[8], abh[8];
#pragma unroll
        for (int r = 0; r < 8; r++) { agl[r] = 0ull; agh[r] = 0ull; abl[r] = 0ull; abh[r] = 0ull; }

#pragma unroll 4
        for (int k2 = 0; k2 < 32; k2++) {
            longlong2 wg = *reinterpret_cast<const longlong2*>(&swg[k2][lane]);
            longlong2 wb = *reinterpret_cast<const longlong2*>(&swb[k2][lane]);
#pragma unroll
            for (int r = 0; r < 8; r++) {
                longlong2 q = *reinterpret_cast<const longlong2*>(
                    g_gp + (size_t)(r0 + r) * 128 + k2 * 4);
                fma2(agl[r], (unsigned long long)wg.x, (unsigned long long)q.x);
                fma2(agh[r], (unsigned long long)wg.y, (unsigned long long)q.x);
                fma2(abl[r], (unsigned long long)wb.x, (unsigned long long)q.y);
                fma2(abh[r], (unsigned long long)wb.y, (unsigned long long)q.y);
            }
        }

#pragma unroll
        for (int r = 0; r < 8; r++) {
            int row = r0 + r;
            float2 a0 = unpack2(agl[r]);
            float2 a1 = unpack2(agh[r]);
            float2 b0 = unpack2(abl[r]);
            float2 b1 = unpack2(abh[r]);
            float gc0 = a0.x + a0.y, gc1 = a1.x + a1.y;
            float bi0 = b0.x + b0.y, bi1 = b1.x + b1.y;
            float xlo = g_cur[(size_t)row * 64 + lane];
            float xhi = g_cur[(size_t)row * 64 + lane + 32];
            float y0 = lrelu(gc0 + sbg[lane] + xlo) + lrelu(bi0 + sbb[lane]);
            float y1 = lrelu(gc1 + sbg[lane + 32] + xhi) + lrelu(bi1 + sbb[lane + 32]);
            float ss = y0 * y0 + y1 * y1;
#pragma unroll
            for (int o = 16; o; o >>= 1) ss += __shfl_xor_sync(0xffffffffu, ss, o);
            float sc = 1.0f / fmaxf(sqrtf(ss), 1e-12f);
            y0 *= sc; y1 *= sc;
            g_cur[(size_t)row * 64 + lane] = y0;
            g_cur[(size_t)row * 64 + lane + 32] = y1;
            if (last) {
                out[(size_t)row * 64 + lane]      = (g_acc[(size_t)row * 64 + lane] + y0) * 0.25f;
                out[(size_t)row * 64 + lane + 32] = (g_acc[(size_t)row * 64 + lane + 32] + y1) * 0.25f;
            } else {
                g_acc[(size_t)row * 64 + lane]      += y0;
                g_acc[(size_t)row * 64 + lane + 32] += y1;
            }
        }
    }
}

// ---------------- launch ----------------
extern "C" void kernel_launch(void* const* d_in, const int* in_sizes, int n_in,
                              void* d_out, int out_size) {
    const float* ue  = (const float*)d_in[0];
    const float* ie  = (const float*)d_in[1];
    const float* Wgc = (const float*)d_in[2];
    const float* bgc = (const float*)d_in[3];
    const float* Wbi = (const float*)d_in[4];
    const float* bbi = (const float*)d_in[5];
    const int*   eu  = (const int*)d_in[6];
    const int*   ei  = (const int*)d_in[7];
    float* out = (float*)d_out;

    k_zero<<<512, 256>>>();
    k_deg<<<(NEQ + 255) / 256, 256>>>(eu, ei);
    k_scalars<<<(NUQ + 255) / 256, 256>>>();
    k_scan<<<2, 1024>>>();
    k_fill<<<(NEQ + 255) / 256, 256>>>(eu, ei);
    k_init<<<4096, 256>>>(ue, ie);

    const int stage_blocks = (NTOT / 2 + 7) / 8;   // 2 rows/warp, 8 warps/block
    for (int l = 0; l < 3; l++) {
        k_stage1<<<stage_blocks, 256>>>();
        k_stage2<<<stage_blocks, 256>>>();
        k_epi<<<592, 256>>>(Wgc + l * 4096, bgc + l * 64, Wbi + l * 4096, bbi + l * 64,
                            out, l == 2 ? 1 : 0);
    }
}

// round 3
// speedup vs baseline: 1.1009x; 1.1009x over previous
#include <cuda_runtime.h>

#define NUQ 100000
#define NIQ 50000
#define NEQ 1000000
#define NTOT (NUQ + NIQ)

// ---------------- scratch (device globals; no allocation allowed) ----------------
__device__ int   g_deg_u[NUQ];
__device__ int   g_deg_i[NIQ];
__device__ int   g_rp_u[NUQ];    // row segment start (arbitrary order, contiguous)
__device__ int   g_rp_i[NIQ];
__device__ int   g_cur_u[NUQ];   // fill ranks
__device__ int   g_cur_i[NIQ];
__device__ int   g_ctr[2];       // global allocators (u, i)
__device__ int   g_col_u[NEQ];   // per-user neighbor items (CSR by user)
__device__ int   g_col_i[NEQ];   // per-item neighbor users (CSR by item)
__device__ float g_su[NUQ], g_iu[NUQ];   // deg_u^-1/2, deg_u^-1
__device__ float g_si[NIQ], g_ii[NIQ];   // deg_i^-1/2, deg_i^-1
__device__ float g_cur[(size_t)NTOT * 64];     // current embeddings (users then items)
__device__ float g_scaled[(size_t)NTOT * 64];  // s_r * cur[r]  (stage1 gather source)
__device__ float g_acc[(size_t)NTOT * 64];     // running sum for the mean
__device__ float g_E[(size_t)NTOT * 64];       // E_items [0,NI), E_users [NI,NI+NU)
__device__ float g_gp[(size_t)NTOT * 128];     // per row: 32 groups of (g0,g1,p0,p1)

// ---------------- helpers ----------------
__device__ __forceinline__ void fma2(unsigned long long& acc, unsigned long long a,
                                     unsigned long long b) {
    asm("fma.rn.f32x2 %0, %1, %2, %0;" : "+l"(acc) : "l"(a), "l"(b));
}
__device__ __forceinline__ float2 unpack2(unsigned long long v) {
    float2 r;
    asm("mov.b64 {%0, %1}, %2;" : "=f"(r.x), "=f"(r.y) : "l"(v));
    return r;
}
__device__ __forceinline__ float lrelu(float x) { return x > 0.f ? x : 0.2f * x; }

// ---------------- setup kernels ----------------
__global__ void k_zero() {
    int i = blockIdx.x * blockDim.x + threadIdx.x;
    int st = gridDim.x * blockDim.x;
    for (int j = i; j < NUQ; j += st) { g_deg_u[j] = 0; g_cur_u[j] = 0; }
    for (int j = i; j < NIQ; j += st) { g_deg_i[j] = 0; g_cur_i[j] = 0; }
    if (i < 2) g_ctr[i] = 0;
}

__global__ void k_deg(const int* __restrict__ eu, const int* __restrict__ ei) {
    int e = blockIdx.x * blockDim.x + threadIdx.x;
    if (e < NEQ) {
        atomicAdd(&g_deg_u[eu[e]], 1);
        atomicAdd(&g_deg_i[ei[e]], 1);
    }
}

// hierarchical segment allocation (order-free CSR row starts) + degree scalars
__global__ void k_alloc() {
    __shared__ int s_tot, s_base;
    int idx = blockIdx.x * blockDim.x + threadIdx.x;
    if (threadIdx.x == 0) s_tot = 0;
    __syncthreads();
    int d = 0, local = 0;
    bool is_u = idx < NUQ;
    bool valid = idx < NTOT;
    if (valid) {
        d = is_u ? g_deg_u[idx] : g_deg_i[idx - NUQ];
        local = atomicAdd(&s_tot, d);
    }
    __syncthreads();
    if (threadIdx.x == 0) {
        // a block never mixes users and items (NUQ % 256 == 0? 100000/256=390.6 -> mixes!)
        s_base = 0;
    }
    __syncthreads();
    // NUQ=100000 is not a multiple of 256, so a block can straddle the u/i boundary.
    // Use two shared counters instead.
    __shared__ int s_tu, s_ti, s_bu, s_bi;
    if (threadIdx.x == 0) { s_tu = 0; s_ti = 0; }
    __syncthreads();
    int loc2 = 0;
    if (valid) loc2 = is_u ? atomicAdd(&s_tu, d) : atomicAdd(&s_ti, d);
    __syncthreads();
    if (threadIdx.x == 0) {
        s_bu = s_tu ? atomicAdd(&g_ctr[0], s_tu) : 0;
        s_bi = s_ti ? atomicAdd(&g_ctr[1], s_ti) : 0;
    }
    __syncthreads();
    if (valid) {
        if (is_u) {
            g_rp_u[idx] = s_bu + loc2;
            g_su[idx] = d > 0 ? rsqrtf((float)d) : 0.f;
            g_iu[idx] = d > 0 ? 1.f / (float)d : 0.f;
        } else {
            int j = idx - NUQ;
            g_rp_i[j] = s_bi + loc2;
            g_si[j] = d > 0 ? rsqrtf((float)d) : 0.f;
            g_ii[j] = d > 0 ? 1.f / (float)d : 0.f;
        }
    }
}

__global__ void k_fill(const int* __restrict__ eu, const int* __restrict__ ei) {
    int e = blockIdx.x * blockDim.x + threadIdx.x;
    if (e < NEQ) {
        int u = eu[e], it = ei[e];
        int pu = g_rp_u[u] + atomicAdd(&g_cur_u[u], 1);
        g_col_u[pu] = it;
        int pi = g_rp_i[it] + atomicAdd(&g_cur_i[it], 1);
        g_col_i[pi] = u;
    }
}

__global__ void k_init(const float* __restrict__ ue, const float* __restrict__ ie) {
    int j = blockIdx.x * blockDim.x + threadIdx.x;
    int st = gridDim.x * blockDim.x;
    const int totu = NUQ * 16;        // float4 count of user part
    const int tot = NTOT * 16;
    const float4* u4 = (const float4*)ue;
    const float4* i4 = (const float4*)ie;
    for (; j < tot; j += st) {
        float4 v = (j < totu) ? u4[j] : i4[j - totu];
        int row = j >> 4;
        float s = (row < NUQ) ? g_su[row] : g_si[row - NUQ];
        ((float4*)g_cur)[j] = v;
        ((float4*)g_acc)[j] = v;
        ((float4*)g_scaled)[j] = make_float4(v.x * s, v.y * s, v.z * s, v.w * s);
    }
}

// ---------------- graph stages: warp = 2 rows, 16 lanes x float4 per row ----------------
// stage1: plain gather-sum of prescaled rows, then * de_inv
__global__ __launch_bounds__(256) void k_stage1() {
    int gw = (blockIdx.x * 256 + threadIdx.x) >> 5;
    int lane = threadIdx.x & 31;
    int sub = lane >> 4, l16 = lane & 15;
    int r = gw * 2 + sub;
    if (r >= NTOT) return;

    int start, deg;
    const int* col;
    const float* src;
    float sc;
    float* dst;
    if (r < NIQ) {            // item rows: E_items[i] = ii[i] * sum su[u]*cur_u[u]
        start = g_rp_i[r]; deg = g_deg_i[r];
        col = g_col_i; src = g_scaled;              // scaled users
        sc = g_ii[r]; dst = g_E + (size_t)r * 64;
    } else {                  // user rows: E_users[u] = iu[u] * sum si[i]*cur_i[i]
        int u = r - NIQ;
        start = g_rp_u[u]; deg = g_deg_u[u];
        col = g_col_u; src = g_scaled + (size_t)NUQ * 64;   // scaled items
        sc = g_iu[u]; dst = g_E + (size_t)(NIQ + u) * 64;
    }
    int end = start + deg;

    float4 a = make_float4(0.f, 0.f, 0.f, 0.f);
    int e = start;
    for (; e + 4 <= end; e += 4) {
        int n0 = col[e], n1 = col[e + 1], n2 = col[e + 2], n3 = col[e + 3];
        float4 v0 = *(const float4*)(src + (size_t)n0 * 64 + l16 * 4);
        float4 v1 = *(const float4*)(src + (size_t)n1 * 64 + l16 * 4);
        float4 v2 = *(const float4*)(src + (size_t)n2 * 64 + l16 * 4);
        float4 v3 = *(const float4*)(src + (size_t)n3 * 64 + l16 * 4);
        a.x += v0.x + v1.x + v2.x + v3.x;
        a.y += v0.y + v1.y + v2.y + v3.y;
        a.z += v0.z + v1.z + v2.z + v3.z;
        a.w += v0.w + v1.w + v2.w + v3.w;
    }
    for (; e < end; e++) {
        int n = col[e];
        float4 v = *(const float4*)(src + (size_t)n * 64 + l16 * 4);
        a.x += v.x; a.y += v.y; a.z += v.z; a.w += v.w;
    }
    *(float4*)(dst + l16 * 4) = make_float4(a.x * sc, a.y * sc, a.z * sc, a.w * sc);
}

__global__ __launch_bounds__(256) void k_stage2() {
    int gw = (blockIdx.x * 256 + threadIdx.x) >> 5;
    int lane = threadIdx.x & 31;
    int sub = lane >> 4, l16 = lane & 15;
    int r = gw * 2 + sub;
    if (r >= NTOT) return;

    int start, deg;
    const int* col;
    const float* src;
    float sc;
    if (r < NUQ) {            // user rows: g_u = su[u] * sum E_items[neighbors]
        start = g_rp_u[r]; deg = g_deg_u[r];
        col = g_col_u; src = g_E; sc = g_su[r];
    } else {                  // item rows: g_i = si[i] * sum E_users[neighbors]
        int i = r - NUQ;
        start = g_rp_i[i]; deg = g_deg_i[i];
        col = g_col_i; src = g_E + (size_t)NIQ * 64; sc = g_si[i];
    }
    int end = start + deg;

    float4 a = make_float4(0.f, 0.f, 0.f, 0.f);
    int e = start;
    for (; e + 4 <= end; e += 4) {
        int n0 = col[e], n1 = col[e + 1], n2 = col[e + 2], n3 = col[e + 3];
        float4 v0 = *(const float4*)(src + (size_t)n0 * 64 + l16 * 4);
        float4 v1 = *(const float4*)(src + (size_t)n1 * 64 + l16 * 4);
        float4 v2 = *(const float4*)(src + (size_t)n2 * 64 + l16 * 4);
        float4 v3 = *(const float4*)(src + (size_t)n3 * 64 + l16 * 4);
        a.x += v0.x + v1.x + v2.x + v3.x;
        a.y += v0.y + v1.y + v2.y + v3.y;
        a.z += v0.z + v1.z + v2.z + v3.z;
        a.w += v0.w + v1.w + v2.w + v3.w;
    }
    for (; e < end; e++) {
        int n = col[e];
        float4 v = *(const float4*)(src + (size_t)n * 64 + l16 * 4);
        a.x += v.x; a.y += v.y; a.z += v.z; a.w += v.w;
    }
    float4 g4 = make_float4(a.x * sc, a.y * sc, a.z * sc, a.w * sc);
    float4 x4 = *(const float4*)(g_cur + (size_t)r * 64 + l16 * 4);
    // per k2 group: (g_2k2, g_2k2+1, p_2k2, p_2k2+1)  (k = 4*l16 .. 4*l16+3)
    float* gpo = g_gp + (size_t)r * 128 + l16 * 8;
    *(float4*)gpo       = make_float4(g4.x, g4.y, g4.x * x4.x, g4.y * x4.y);
    *(float4*)(gpo + 4) = make_float4(g4.z, g4.w, g4.z * x4.z, g4.w * x4.w);
}

// ---------------- epilogue: dual GEMV + leaky relu + row norm + mean accum ----------------
__global__ __launch_bounds__(256) void k_epi(const float* __restrict__ Wgc,
                                             const float* __restrict__ bgc,
                                             const float* __restrict__ Wbi,
                                             const float* __restrict__ bbi,
                                             float* __restrict__ out, int last) {
    // swg[k2][lane] = (W[lane][2k2], W[lane][2k2+1], W[lane+32][2k2], W[lane+32][2k2+1])
    __shared__ float4 swg[32][32];
    __shared__ float4 swb[32][32];
    __shared__ float sbg[64], sbb[64];
    for (int idx = threadIdx.x; idx < 1024; idx += 256) {
        int d = idx >> 5, k2 = idx & 31, k = 2 * k2;
        swg[k2][d] = make_float4(Wgc[d * 64 + k], Wgc[d * 64 + k + 1],
                                 Wgc[(d + 32) * 64 + k], Wgc[(d + 32) * 64 + k + 1]);
        swb[k2][d] = make_float4(Wbi[d * 64 + k], Wbi[d * 64 + k + 1],
                                 Wbi[(d + 32) * 64 + k], Wbi[(d + 32) * 64 + k + 1]);
    }
    if (threadIdx.x < 64) { sbg[threadIdx.x] = bgc[threadIdx.x]; sbb[threadIdx.x] = bbi[threadIdx.x]; }
    __syncthreads();

    int lane = threadIdx.x & 31;
    int gw = (blockIdx.x * 256 + threadIdx.x) >> 5;
    int nw = gridDim.x * 8;
    const int ntask = NTOT / 8;   // 150000 % 8 == 0

    for (int t = gw; t < ntask; t += nw) {
        int r0 = t * 8;
        unsigned long long agl[8], agh[8], abl[8], abh[8];
#pragma unroll
        for (int r = 0; r < 8; r++) { agl[r] = 0ull; agh[r] = 0ull; abl[r] = 0ull; abh[r] = 0ull; }

#pragma unroll 4
        for (int k2 = 0; k2 < 32; k2++) {
            longlong2 wg = *reinterpret_cast<const longlong2*>(&swg[k2][lane]);
            longlong2 wb = *reinterpret_cast<const longlong2*>(&swb[k2][lane]);
#pragma unroll
            for (int r = 0; r < 8; r++) {
                longlong2 q = *reinterpret_cast<const longlong2*>(
                    g_gp + (size_t)(r0 + r) * 128 + k2 * 4);
                fma2(agl[r], (unsigned long long)wg.x, (unsigned long long)q.x);
                fma2(agh[r], (unsigned long long)wg.y, (unsigned long long)q.x);
                fma2(abl[r], (unsigned long long)wb.x, (unsigned long long)q.y);
                fma2(abh[r], (unsigned long long)wb.y, (unsigned long long)q.y);
            }
        }

#pragma unroll
        for (int r = 0; r < 8; r++) {
            int row = r0 + r;
            float2 a0 = unpack2(agl[r]);
            float2 a1 = unpack2(agh[r]);
            float2 b0 = unpack2(abl[r]);
            float2 b1 = unpack2(abh[r]);
            float gc0 = a0.x + a0.y, gc1 = a1.x + a1.y;
            float bi0 = b0.x + b0.y, bi1 = b1.x + b1.y;
            float xlo = g_cur[(size_t)row * 64 + lane];
            float xhi = g_cur[(size_t)row * 64 + lane + 32];
            float y0 = lrelu(gc0 + sbg[lane] + xlo) + lrelu(bi0 + sbb[lane]);
            float y1 = lrelu(gc1 + sbg[lane + 32] + xhi) + lrelu(bi1 + sbb[lane + 32]);
            float ss = y0 * y0 + y1 * y1;
#pragma unroll
            for (int o = 16; o; o >>= 1) ss += __shfl_xor_sync(0xffffffffu, ss, o);
            float sc = 1.0f / fmaxf(sqrtf(ss), 1e-12f);
            y0 *= sc; y1 *= sc;
            g_cur[(size_t)row * 64 + lane] = y0;
            g_cur[(size_t)row * 64 + lane + 32] = y1;
            if (last) {
                out[(size_t)row * 64 + lane]      = (g_acc[(size_t)row * 64 + lane] + y0) * 0.25f;
                out[(size_t)row * 64 + lane + 32] = (g_acc[(size_t)row * 64 + lane + 32] + y1) * 0.25f;
            } else {
                float s = (row < NUQ) ? g_su[row] : g_si[row - NUQ];
                g_scaled[(size_t)row * 64 + lane]      = y0 * s;
                g_scaled[(size_t)row * 64 + lane + 32] = y1 * s;
                g_acc[(size_t)row * 64 + lane]      += y0;
                g_acc[(size_t)row * 64 + lane + 32] += y1;
            }
        }
    }
}

// ---------------- launch ----------------
extern "C" void kernel_launch(void* const* d_in, const int* in_sizes, int n_in,
                              void* d_out, int out_size) {
    const float* ue  = (const float*)d_in[0];
    const float* ie  = (const float*)d_in[1];
    const float* Wgc = (const float*)d_in[2];
    const float* bgc = (const float*)d_in[3];
    const float* Wbi = (const float*)d_in[4];
    const float* bbi = (const float*)d_in[5];
    const int*   eu  = (const int*)d_in[6];
    const int*   ei  = (const int*)d_in[7];
    float* out = (float*)d_out;

    k_zero<<<512, 256>>>();
    k_deg<<<(NEQ + 255) / 256, 256>>>(eu, ei);
    k_alloc<<<(NTOT + 255) / 256, 256>>>();
    k_fill<<<(NEQ + 255) / 256, 256>>>(eu, ei);
    k_init<<<4096, 256>>>(ue, ie);

    const int stage_blocks = (NTOT / 2 + 7) / 8;   // 2 rows/warp, 8 warps/block
    for (int l = 0; l < 3; l++) {
        k_stage1<<<stage_blocks, 256>>>();
        k_stage2<<<stage_blocks, 256>>>();
        k_epi<<<592, 256>>>(Wgc + l * 4096, bgc + l * 64, Wbi + l * 4096, bbi + l * 64,
                            out, l == 2 ? 1 : 0);
    }
}

// round 4
// speedup vs baseline: 1.1225x; 1.0196x over previous
#include <cuda_runtime.h>
#include <cuda_fp16.h>

#define NUQ 100000
#define NIQ 50000
#define NEQ 1000000
#define NTOT (NUQ + NIQ)

// ---------------- scratch (device globals; no allocation allowed) ----------------
__device__ int   g_deg_u[NUQ];
__device__ int   g_deg_i[NIQ];
__device__ int   g_rp_u[NUQ];    // row segment start (arbitrary order, contiguous)
__device__ int   g_rp_i[NIQ];
__device__ int   g_cur_u[NUQ];   // fill ranks
__device__ int   g_cur_i[NIQ];
__device__ int   g_ctr[2];       // global allocators (u, i)
__device__ int   g_col_u[NEQ];   // per-user neighbor items (CSR by user)
__device__ int   g_col_i[NEQ];   // per-item neighbor users (CSR by item)
__device__ float g_su[NUQ], g_iu[NUQ];   // deg_u^-1/2, deg_u^-1
__device__ float g_si[NIQ], g_ii[NIQ];   // deg_i^-1/2, deg_i^-1
__device__ float g_cur[(size_t)NTOT * 64];      // current embeddings (users then items)
__device__ __half g_scaled_h[(size_t)NTOT * 64]; // s_r * cur[r]  (stage1 gather source, fp16)
__device__ __half g_E_h[(size_t)NTOT * 64];      // E (stage2 gather source, fp16)
__device__ float g_acc[(size_t)NTOT * 64];      // running sum for the mean
__device__ float g_gp[(size_t)NTOT * 128];      // per row: 32 groups of (g0,g1,p0,p1)

// ---------------- helpers ----------------
__device__ __forceinline__ void fma2(unsigned long long& acc, unsigned long long a,
                                     unsigned long long b) {
    asm("fma.rn.f32x2 %0, %1, %2, %0;" : "+l"(acc) : "l"(a), "l"(b));
}
__device__ __forceinline__ float2 unpack2(unsigned long long v) {
    float2 r;
    asm("mov.b64 {%0, %1}, %2;" : "=f"(r.x), "=f"(r.y) : "l"(v));
    return r;
}
__device__ __forceinline__ float lrelu(float x) { return x > 0.f ? x : 0.2f * x; }

// accumulate 4 halves (packed in uint2) into float4
__device__ __forceinline__ void acc_h4(float4& a, uint2 q) {
    __half2 h0 = *reinterpret_cast<__half2*>(&q.x);
    __half2 h1 = *reinterpret_cast<__half2*>(&q.y);
    float2 f0 = __half22float2(h0);
    float2 f1 = __half22float2(h1);
    a.x += f0.x; a.y += f0.y; a.z += f1.x; a.w += f1.y;
}
__device__ __forceinline__ uint2 pack_h4(float x, float y, float z, float w) {
    uint2 q;
    __half2 h0 = __floats2half2_rn(x, y);
    __half2 h1 = __floats2half2_rn(z, w);
    q.x = *reinterpret_cast<unsigned*>(&h0);
    q.y = *reinterpret_cast<unsigned*>(&h1);
    return q;
}

// ---------------- setup kernels ----------------
__global__ void k_zero() {
    int i = blockIdx.x * blockDim.x + threadIdx.x;
    int st = gridDim.x * blockDim.x;
    for (int j = i; j < NUQ; j += st) { g_deg_u[j] = 0; g_cur_u[j] = 0; }
    for (int j = i; j < NIQ; j += st) { g_deg_i[j] = 0; g_cur_i[j] = 0; }
    if (i < 2) g_ctr[i] = 0;
}

__global__ void k_deg(const int* __restrict__ eu, const int* __restrict__ ei) {
    int e = blockIdx.x * blockDim.x + threadIdx.x;
    if (e < NEQ) {
        atomicAdd(&g_deg_u[eu[e]], 1);
        atomicAdd(&g_deg_i[ei[e]], 1);
    }
}

// hierarchical segment allocation (order-free CSR row starts) + degree scalars
__global__ void k_alloc() {
    __shared__ int s_tu, s_ti, s_bu, s_bi;
    int idx = blockIdx.x * blockDim.x + threadIdx.x;
    if (threadIdx.x == 0) { s_tu = 0; s_ti = 0; }
    __syncthreads();
    bool is_u = idx < NUQ;
    bool valid = idx < NTOT;
    int d = 0, loc = 0;
    if (valid) {
        d = is_u ? g_deg_u[idx] : g_deg_i[idx - NUQ];
        loc = is_u ? atomicAdd(&s_tu, d) : atomicAdd(&s_ti, d);
    }
    __syncthreads();
    if (threadIdx.x == 0) {
        s_bu = s_tu ? atomicAdd(&g_ctr[0], s_tu) : 0;
        s_bi = s_ti ? atomicAdd(&g_ctr[1], s_ti) : 0;
    }
    __syncthreads();
    if (valid) {
        if (is_u) {
            g_rp_u[idx] = s_bu + loc;
            g_su[idx] = d > 0 ? rsqrtf((float)d) : 0.f;
            g_iu[idx] = d > 0 ? 1.f / (float)d : 0.f;
        } else {
            int j = idx - NUQ;
            g_rp_i[j] = s_bi + loc;
            g_si[j] = d > 0 ? rsqrtf((float)d) : 0.f;
            g_ii[j] = d > 0 ? 1.f / (float)d : 0.f;
        }
    }
}

__global__ void k_fill(const int* __restrict__ eu, const int* __restrict__ ei) {
    int e = blockIdx.x * blockDim.x + threadIdx.x;
    if (e < NEQ) {
        int u = eu[e], it = ei[e];
        int pu = g_rp_u[u] + atomicAdd(&g_cur_u[u], 1);
        g_col_u[pu] = it;
        int pi = g_rp_i[it] + atomicAdd(&g_cur_i[it], 1);
        g_col_i[pi] = u;
    }
}

__global__ void k_init(const float* __restrict__ ue, const float* __restrict__ ie) {
    int j = blockIdx.x * blockDim.x + threadIdx.x;
    int st = gridDim.x * blockDim.x;
    const int totu = NUQ * 16;        // float4 count of user part
    const int tot = NTOT * 16;
    const float4* u4 = (const float4*)ue;
    const float4* i4 = (const float4*)ie;
    for (; j < tot; j += st) {
        float4 v = (j < totu) ? u4[j] : i4[j - totu];
        int row = j >> 4;
        float s = (row < NUQ) ? g_su[row] : g_si[row - NUQ];
        ((float4*)g_cur)[j] = v;
        ((float4*)g_acc)[j] = v;
        ((uint2*)g_scaled_h)[j] = pack_h4(v.x * s, v.y * s, v.z * s, v.w * s);
    }
}

// ---------------- graph stages: warp = 2 rows, 16 lanes x 4 halves per row ----------------
// stage1: gather-sum of prescaled fp16 rows, then * de_inv, store fp16 E
__global__ __launch_bounds__(256) void k_stage1() {
    int gw = (blockIdx.x * 256 + threadIdx.x) >> 5;
    int lane = threadIdx.x & 31;
    int sub = lane >> 4, l16 = lane & 15;
    int r = gw * 2 + sub;
    if (r >= NTOT) return;

    int start, deg;
    const int* col;
    const __half* src;
    float sc;
    __half* dst;
    if (r < NIQ) {            // item rows: E_items[i] = ii[i] * sum su[u]*cur_u[u]
        start = g_rp_i[r]; deg = g_deg_i[r];
        col = g_col_i; src = g_scaled_h;              // scaled users
        sc = g_ii[r]; dst = g_E_h + (size_t)r * 64;
    } else {                  // user rows: E_users[u] = iu[u] * sum si[i]*cur_i[i]
        int u = r - NIQ;
        start = g_rp_u[u]; deg = g_deg_u[u];
        col = g_col_u; src = g_scaled_h + (size_t)NUQ * 64;   // scaled items
        sc = g_iu[u]; dst = g_E_h + (size_t)(NIQ + u) * 64;
    }
    int end = start + deg;

    float4 a = make_float4(0.f, 0.f, 0.f, 0.f);
    int e = start;
    for (; e + 4 <= end; e += 4) {
        int n0 = col[e], n1 = col[e + 1], n2 = col[e + 2], n3 = col[e + 3];
        uint2 q0 = *(const uint2*)(src + (size_t)n0 * 64 + l16 * 4);
        uint2 q1 = *(const uint2*)(src + (size_t)n1 * 64 + l16 * 4);
        uint2 q2 = *(const uint2*)(src + (size_t)n2 * 64 + l16 * 4);
        uint2 q3 = *(const uint2*)(src + (size_t)n3 * 64 + l16 * 4);
        acc_h4(a, q0); acc_h4(a, q1); acc_h4(a, q2); acc_h4(a, q3);
    }
    for (; e < end; e++) {
        int n = col[e];
        uint2 q = *(const uint2*)(src + (size_t)n * 64 + l16 * 4);
        acc_h4(a, q);
    }
    *(uint2*)(dst + l16 * 4) = pack_h4(a.x * sc, a.y * sc, a.z * sc, a.w * sc);
}

__global__ __launch_bounds__(256) void k_stage2() {
    int gw = (blockIdx.x * 256 + threadIdx.x) >> 5;
    int lane = threadIdx.x & 31;
    int sub = lane >> 4, l16 = lane & 15;
    int r = gw * 2 + sub;
    if (r >= NTOT) return;

    int start, deg;
    const int* col;
    const __half* src;
    float sc;
    if (r < NUQ) {            // user rows: g_u = su[u] * sum E_items[neighbors]
        start = g_rp_u[r]; deg = g_deg_u[r];
        col = g_col_u; src = g_E_h; sc = g_su[r];
    } else {                  // item rows: g_i = si[i] * sum E_users[neighbors]
        int i = r - NUQ;
        start = g_rp_i[i]; deg = g_deg_i[i];
        col = g_col_i; src = g_E_h + (size_t)NIQ * 64; sc = g_si[i];
    }
    int end = start + deg;

    float4 a = make_float4(0.f, 0.f, 0.f, 0.f);
    int e = start;
    for (; e + 4 <= end; e += 4) {
        int n0 = col[e], n1 = col[e + 1], n2 = col[e + 2], n3 = col[e + 3];
        uint2 q0 = *(const uint2*)(src + (size_t)n0 * 64 + l16 * 4);
        uint2 q1 = *(const uint2*)(src + (size_t)n1 * 64 + l16 * 4);
        uint2 q2 = *(const uint2*)(src + (size_t)n2 * 64 + l16 * 4);
        uint2 q3 = *(const uint2*)(src + (size_t)n3 * 64 + l16 * 4);
        acc_h4(a, q0); acc_h4(a, q1); acc_h4(a, q2); acc_h4(a, q3);
    }
    for (; e < end; e++) {
        int n = col[e];
        uint2 q = *(const uint2*)(src + (size_t)n * 64 + l16 * 4);
        acc_h4(a, q);
    }
    float4 g4 = make_float4(a.x * sc, a.y * sc, a.z * sc, a.w * sc);
    float4 x4 = *(const float4*)(g_cur + (size_t)r * 64 + l16 * 4);
    // per k2 group: (g_2k2, g_2k2+1, p_2k2, p_2k2+1)  (k = 4*l16 .. 4*l16+3)
    float* gpo = g_gp + (size_t)r * 128 + l16 * 8;
    *(float4*)gpo       = make_float4(g4.x, g4.y, g4.x * x4.x, g4.y * x4.y);
    *(float4*)(gpo + 4) = make_float4(g4.z, g4.w, g4.z * x4.z, g4.w * x4.w);
}

// ---------------- epilogue: dual GEMV + leaky relu + row norm + mean accum ----------------
__global__ __launch_bounds__(256) void k_epi(const float* __restrict__ Wgc,
                                             const float* __restrict__ bgc,
                                             const float* __restrict__ Wbi,
                                             const float* __restrict__ bbi,
                                             float* __restrict__ out, int last) {
    // swg[k2][lane] = (W[lane][2k2], W[lane][2k2+1], W[lane+32][2k2], W[lane+32][2k2+1])
    __shared__ float4 swg[32][32];
    __shared__ float4 swb[32][32];
    __shared__ float sbg[64], sbb[64];
    for (int idx = threadIdx.x; idx < 1024; idx += 256) {
        int d = idx >> 5, k2 = idx & 31, k = 2 * k2;
        swg[k2][d] = make_float4(Wgc[d * 64 + k], Wgc[d * 64 + k + 1],
                                 Wgc[(d + 32) * 64 + k], Wgc[(d + 32) * 64 + k + 1]);
        swb[k2][d] = make_float4(Wbi[d * 64 + k], Wbi[d * 64 + k + 1],
                                 Wbi[(d + 32) * 64 + k], Wbi[(d + 32) * 64 + k + 1]);
    }
    if (threadIdx.x < 64) { sbg[threadIdx.x] = bgc[threadIdx.x]; sbb[threadIdx.x] = bbi[threadIdx.x]; }
    __syncthreads();

    int lane = threadIdx.x & 31;
    int gw = (blockIdx.x * 256 + threadIdx.x) >> 5;
    int nw = gridDim.x * 8;
    const int ntask = NTOT / 8;   // 150000 % 8 == 0

    for (int t = gw; t < ntask; t += nw) {
        int r0 = t * 8;
        unsigned long long agl[8], agh[8], abl[8], abh[8];
#pragma unroll
        for (int r = 0; r < 8; r++) { agl[r] = 0ull; agh[r] = 0ull; abl[r] = 0ull; abh[r] = 0ull; }

#pragma unroll 4
        for (int k2 = 0; k2 < 32; k2++) {
            longlong2 wg = *reinterpret_cast<const longlong2*>(&swg[k2][lane]);
            longlong2 wb = *reinterpret_cast<const longlong2*>(&swb[k2][lane]);
#pragma unroll
            for (int r = 0; r < 8; r++) {
                longlong2 q = *reinterpret_cast<const longlong2*>(
                    g_gp + (size_t)(r0 + r) * 128 + k2 * 4);
                fma2(agl[r], (unsigned long long)wg.x, (unsigned long long)q.x);
                fma2(agh[r], (unsigned long long)wg.y, (unsigned long long)q.x);
                fma2(abl[r], (unsigned long long)wb.x, (unsigned long long)q.y);
                fma2(abh[r], (unsigned long long)wb.y, (unsigned long long)q.y);
            }
        }

#pragma unroll
        for (int r = 0; r < 8; r++) {
            int row = r0 + r;
            float2 a0 = unpack2(agl[r]);
            float2 a1 = unpack2(agh[r]);
            float2 b0 = unpack2(abl[r]);
            float2 b1 = unpack2(abh[r]);
            float gc0 = a0.x + a0.y, gc1 = a1.x + a1.y;
            float bi0 = b0.x + b0.y, bi1 = b1.x + b1.y;
            float xlo = g_cur[(size_t)row * 64 + lane];
            float xhi = g_cur[(size_t)row * 64 + lane + 32];
            float y0 = lrelu(gc0 + sbg[lane] + xlo) + lrelu(bi0 + sbb[lane]);
            float y1 = lrelu(gc1 + sbg[lane + 32] + xhi) + lrelu(bi1 + sbb[lane + 32]);
            float ss = y0 * y0 + y1 * y1;
#pragma unroll
            for (int o = 16; o; o >>= 1) ss += __shfl_xor_sync(0xffffffffu, ss, o);
            float sc = 1.0f / fmaxf(sqrtf(ss), 1e-12f);
            y0 *= sc; y1 *= sc;
            g_cur[(size_t)row * 64 + lane] = y0;
            g_cur[(size_t)row * 64 + lane + 32] = y1;
            if (last) {
                out[(size_t)row * 64 + lane]      = (g_acc[(size_t)row * 64 + lane] + y0) * 0.25f;
                out[(size_t)row * 64 + lane + 32] = (g_acc[(size_t)row * 64 + lane + 32] + y1) * 0.25f;
            } else {
                float s = (row < NUQ) ? g_su[row] : g_si[row - NUQ];
                g_scaled_h[(size_t)row * 64 + lane]      = __float2half(y0 * s);
                g_scaled_h[(size_t)row * 64 + lane + 32] = __float2half(y1 * s);
                g_acc[(size_t)row * 64 + lane]      += y0;
                g_acc[(size_t)row * 64 + lane + 32] += y1;
            }
        }
    }
}

// ---------------- launch ----------------
extern "C" void kernel_launch(void* const* d_in, const int* in_sizes, int n_in,
                              void* d_out, int out_size) {
    const float* ue  = (const float*)d_in[0];
    const float* ie  = (const float*)d_in[1];
    const float* Wgc = (const float*)d_in[2];
    const float* bgc = (const float*)d_in[3];
    const float* Wbi = (const float*)d_in[4];
    const float* bbi = (const float*)d_in[5];
    const int*   eu  = (const int*)d_in[6];
    const int*   ei  = (const int*)d_in[7];
    float* out = (float*)d_out;

    k_zero<<<512, 256>>>();
    k_deg<<<(NEQ + 255) / 256, 256>>>(eu, ei);
    k_alloc<<<(NTOT + 255) / 256, 256>>>();
    k_fill<<<(NEQ + 255) / 256, 256>>>(eu, ei);
    k_init<<<4096, 256>>>(ue, ie);

    const int stage_blocks = (NTOT / 2 + 7) / 8;   // 2 rows/warp, 8 warps/block
    for (int l = 0; l < 3; l++) {
        k_stage1<<<stage_blocks, 256>>>();
        k_stage2<<<stage_blocks, 256>>>();
        k_epi<<<592, 256>>>(Wgc + l * 4096, bgc + l * 64, Wbi + l * 4096, bbi + l * 64,
                            out, l == 2 ? 1 : 0);
    }
}